// round 12
// baseline (speedup 1.0000x reference)
#include <cuda_runtime.h>
#include <cuda_fp16.h>
#include <cstdint>

// Problem constants
#define Tn 1024
#define Dn 2048
#define Hn 7168
#define En 8
#define Kn 2
#define Pn (Tn * Kn)                   // 2048 (token,k) pairs
#define TILE_M 128
#define MAX_SLOTS (Pn + En * TILE_M)   // 3072
#define MAX_TILES (Pn / TILE_M + En)   // 24

#define G1_KIT (Dn / 64)               // 32 K-chunks of 64
#define G2_KIT (Hn / 64)               // 112 K-chunks of 64

// Dynamic smem: 2 stages x 32KB (A 16KB + B 16KB) ; epilogue overlay 128x132 fp32
#define SMEM_REQ 68608

// Scratch (device globals; no allocation allowed)
__device__ int   g_slot_token[MAX_SLOTS];
__device__ float g_slot_w[MAX_SLOTS];
__device__ int   g_tile_expert[MAX_TILES];
__device__ int   g_tile_base[MAX_TILES];
// single fp16 plane for the A-side operands
__device__ __align__(16) unsigned short g_x_h[(size_t)Tn * Dn];
__device__ __align__(16) unsigned short g_hact_h[(size_t)MAX_SLOTS * Hn];

// ---------------------------------------------------------------------------
// Helpers
// ---------------------------------------------------------------------------
__device__ __forceinline__ uint32_t smem_u32(const void* p) {
    uint32_t a;
    asm("{ .reg .u64 t; cvta.to.shared.u64 t, %1; cvt.u32.u64 %0, t; }"
        : "=r"(a) : "l"(p));
    return a;
}

__device__ __forceinline__ uint32_t sw128(uint32_t o) {
    return o ^ (((o >> 7) & 7u) << 4);
}
__device__ __forceinline__ uint32_t sw256(uint32_t o) {
    return o ^ (((o >> 8) & 7u) << 4);
}

__device__ __forceinline__ void cpa16(uint32_t dst, const void* src, uint32_t sz) {
    asm volatile("cp.async.cg.shared.global [%0], [%1], 16, %2;"
                 :: "r"(dst), "l"(src), "r"(sz) : "memory");
}
#define CP_COMMIT() asm volatile("cp.async.commit_group;" ::: "memory")
#define CP_WAIT0()  asm volatile("cp.async.wait_group 0;" ::: "memory")

__device__ __forceinline__ void ldsm4(uint32_t* r, uint32_t a) {
    asm volatile("ldmatrix.sync.aligned.m8n8.x4.shared.b16 {%0,%1,%2,%3}, [%4];"
        : "=r"(r[0]), "=r"(r[1]), "=r"(r[2]), "=r"(r[3]) : "r"(a));
}
__device__ __forceinline__ void ldsm4t(uint32_t* r, uint32_t a) {
    asm volatile("ldmatrix.sync.aligned.m8n8.x4.trans.shared.b16 {%0,%1,%2,%3}, [%4];"
        : "=r"(r[0]), "=r"(r[1]), "=r"(r[2]), "=r"(r[3]) : "r"(a));
}
__device__ __forceinline__ void mma16816h(float* c, const uint32_t* a,
                                          uint32_t b0, uint32_t b1) {
    asm volatile(
        "mma.sync.aligned.m16n8k16.row.col.f32.f16.f16.f32 "
        "{%0,%1,%2,%3}, {%4,%5,%6,%7}, {%8,%9}, {%0,%1,%2,%3};"
        : "+f"(c[0]), "+f"(c[1]), "+f"(c[2]), "+f"(c[3])
        : "r"(a[0]), "r"(a[1]), "r"(a[2]), "r"(a[3]), "r"(b0), "r"(b1));
}

__device__ __forceinline__ uint32_t ph_rn(float a, float b) {
    __half2 h = __floats2half2_rn(a, b);
    return *(uint32_t*)&h;
}

// ---------------------------------------------------------------------------
// x convert: fp32 -> fp16 plane (4 MB, ~4us)
// ---------------------------------------------------------------------------
__global__ void splitx_kernel(const float4* __restrict__ src, int n4) {
    int i = blockIdx.x * blockDim.x + threadIdx.x;
    if (i < n4) {
        float4 v = __ldg(src + i);
        ((uint2*)g_x_h)[i] = make_uint2(ph_rn(v.x, v.y), ph_rn(v.z, v.w));
    }
}

// ---------------------------------------------------------------------------
// Routing
// ---------------------------------------------------------------------------
__global__ void route_kernel(const int* __restrict__ sel,
                             const float* __restrict__ wts) {
    __shared__ int s_e[Pn];
    __shared__ int s_cnt[En];
    __shared__ int s_base[En];
    int tid = threadIdx.x;

    if (tid < En) s_cnt[tid] = 0;
    __syncthreads();
    for (int i = tid; i < Pn; i += blockDim.x) {
        int e = sel[i];
        s_e[i] = e;
        atomicAdd(&s_cnt[e], 1);
    }
    __syncthreads();
    if (tid == 0) {
        int base = 0, tile = 0;
        for (int e = 0; e < En; e++) {
            s_base[e] = base;
            int padded = ((s_cnt[e] + TILE_M - 1) / TILE_M) * TILE_M;
            for (int m = 0; m < padded; m += TILE_M) {
                g_tile_expert[tile] = e;
                g_tile_base[tile]   = base + m;
                tile++;
            }
            base += padded;
        }
        for (; tile < MAX_TILES; tile++) g_tile_expert[tile] = -1;
    }
    __syncthreads();
    for (int s = tid; s < MAX_SLOTS; s += blockDim.x) g_slot_token[s] = -1;
    __syncthreads();
    for (int i = tid; i < Pn; i += blockDim.x) {
        int e = s_e[i];
        int rank = 0;
        for (int j = 0; j < i; j++) rank += (s_e[j] == e) ? 1 : 0;
        int slot = s_base[e] + rank;
        g_slot_token[slot] = i / Kn;
        g_slot_w[slot]     = wts[i];
    }
}

__global__ void zero_kernel(float* __restrict__ out) {
    int i = blockIdx.x * blockDim.x + threadIdx.x;
    out[i] = 0.0f;
}

// ---------------------------------------------------------------------------
// GEMM1: hact[slot, h0+c] = silu(x.W1^T) * (x.W3^T)
// 256 threads, CTA 128x128 (n 0-63 gate / 64-127 up), BK=64.
// 8 warps = 2m x 2n x 2k (K-split): warps 0-3 own k16{0,1}, 4-7 own k16{2,3};
// every warp keeps the 64x64 tile. Epilogue reduces the two k-halves in smem.
// ---------------------------------------------------------------------------
__global__ __launch_bounds__(256, 1) void gemm1_kernel(
    const float* __restrict__ w1,
    const float* __restrict__ w3) {
    int e = g_tile_expert[blockIdx.x];
    if (e < 0) return;
    int base = g_tile_base[blockIdx.x];
    int h0 = blockIdx.y * 64;

    extern __shared__ char dsm[];
    __shared__ int s_tok[TILE_M];
    uint32_t raw = smem_u32(dsm);
    uint32_t sb = (raw + 1023u) & ~1023u;
    char* sp = dsm + (sb - raw);

    int tid = threadIdx.x;
    if (tid < TILE_M) s_tok[tid] = g_slot_token[base + tid];
    __syncthreads();

    const int warp = tid >> 5, lane = tid & 31;
    const int ks = warp >> 2;            // k-half 0/1
    const int wm = (warp >> 1) & 1, wn = warp & 1;

    // A cp.async: row r = t>>1, 64B run ((t&1)*64 .. +64) of the 128B row
    const int arow = tid >> 1;
    const int tokA = s_tok[arow];
    const unsigned short* aP =
        g_x_h + (size_t)(tokA < 0 ? 0 : tokA) * Dn + (tid & 1) * 32;
    const uint32_t avz = (tokA >= 0) ? 16u : 0u;
    uint32_t adst[4];
#pragma unroll
    for (int j = 0; j < 4; j++)
        adst[j] = sw128((uint32_t)arow * 128u + (uint32_t)((tid & 1) * 4 + j) * 16u);

    // B LDG: g 0-7: half g>>2 (w1/w3), local row (g&3)*16+(t>>4), seg t&15
    const int blr = tid >> 4, bseg = tid & 15;
    const float* b1P = w1 + ((size_t)e * Hn + h0 + blr) * Dn + bseg * 4;
    const float* b3P = w3 + ((size_t)e * Hn + h0 + blr) * Dn + bseg * 4;
    uint32_t bdst[8];
#pragma unroll
    for (int g = 0; g < 8; g++) {
        uint32_t br = (uint32_t)((g >> 2) * 64 + (g & 3) * 16 + blr);
        bdst[g] = sw128(br * 128u + (uint32_t)(bseg >> 1) * 16u)
                + (uint32_t)(bseg & 1) * 8u;
    }

    // ldmatrix lane offsets
    const uint32_t a_m  = (uint32_t)(lane & 15);
    const uint32_t a_kc = (uint32_t)(lane >> 4);
    const uint32_t b_n  = (uint32_t)((lane & 7) | ((lane >> 4) << 3));
    const uint32_t b_kc = (uint32_t)((lane >> 3) & 1);

    float C[4][8][4];
#pragma unroll
    for (int i = 0; i < 4; i++)
#pragma unroll
        for (int j = 0; j < 8; j++)
#pragma unroll
            for (int k = 0; k < 4; k++) C[i][j][k] = 0.f;

    float4 Br[8];

#define LDGB1(c) do {                                                       \
    _Pragma("unroll")                                                       \
    for (int g = 0; g < 4; g++)                                             \
        Br[g] = __ldg((const float4*)(b1P + (size_t)(g) * 16 * Dn + (c) * 64)); \
    _Pragma("unroll")                                                       \
    for (int g = 4; g < 8; g++)                                             \
        Br[g] = __ldg((const float4*)(b3P + (size_t)(g - 4) * 16 * Dn + (c) * 64)); \
} while (0)

#define CPA1(c, st) do {                                                    \
    uint32_t Ab = sb + (st) * 32768u;                                       \
    const unsigned short* as = aP + (c) * 64;                               \
    _Pragma("unroll")                                                       \
    for (int j = 0; j < 4; j++)                                             \
        cpa16(Ab + adst[j], as + j * 8, avz);                               \
    CP_COMMIT();                                                            \
} while (0)

#define STSB1(st) do {                                                      \
    char* Bb = sp + (st) * 32768 + 16384;                                   \
    _Pragma("unroll")                                                       \
    for (int g = 0; g < 8; g++) {                                           \
        float4 v = Br[g];                                                   \
        *(uint2*)(Bb + bdst[g]) = make_uint2(ph_rn(v.x, v.y), ph_rn(v.z, v.w)); \
    }                                                                       \
} while (0)

#define COMP1(st) do {                                                      \
    uint32_t Au = sb + (st) * 32768u;                                       \
    uint32_t Bu = Au + 16384u;                                              \
    _Pragma("unroll")                                                       \
    for (int k16l = 0; k16l < 2; k16l++) {                                  \
        int kk = ks * 2 + k16l;                                             \
        uint32_t aH[4][4];                                                  \
        _Pragma("unroll")                                                   \
        for (int mt = 0; mt < 4; mt++) {                                    \
            uint32_t o = (uint32_t)(wm * 64 + mt * 16 + a_m) * 128u + kk * 32u + a_kc * 16u; \
            ldsm4(aH[mt], Au + sw128(o));                                   \
        }                                                                   \
        _Pragma("unroll")                                                   \
        for (int ng = 0; ng < 4; ng++) {                                    \
            uint32_t o = (uint32_t)(wn * 64 + ng * 16 + b_n) * 128u + kk * 32u + b_kc * 16u; \
            uint32_t bH[4];                                                 \
            ldsm4(bH, Bu + sw128(o));                                       \
            _Pragma("unroll")                                               \
            for (int mt = 0; mt < 4; mt++) {                                \
                mma16816h(C[mt][2 * ng],     aH[mt], bH[0], bH[1]);         \
                mma16816h(C[mt][2 * ng + 1], aH[mt], bH[2], bH[3]);         \
            }                                                               \
        }                                                                   \
    }                                                                       \
} while (0)

    LDGB1(0);
    CPA1(0, 0);
    STSB1(0);
    LDGB1(1);
    for (int c = 0; c < G1_KIT; c++) {
        int st = c & 1;
        CP_WAIT0();
        __syncthreads();
        if (c + 1 < G1_KIT) CPA1(c + 1, st ^ 1);
        COMP1(st);
        if (c + 1 < G1_KIT) STSB1(st ^ 1);
        if (c + 2 < G1_KIT) LDGB1(c + 2);
    }
    __syncthreads();

    // Epilogue: k-half reduce through smem, then SiLU
    float* sc = (float*)sp;
    if (ks == 0) {
#pragma unroll
        for (int mt = 0; mt < 4; mt++)
#pragma unroll
            for (int nt = 0; nt < 8; nt++) {
                int r0 = wm * 64 + mt * 16 + (lane >> 2);
                int cc = wn * 64 + nt * 8 + (lane & 3) * 2;
                sc[r0 * 132 + cc]       = C[mt][nt][0];
                sc[r0 * 132 + cc + 1]   = C[mt][nt][1];
                sc[(r0 + 8) * 132 + cc]     = C[mt][nt][2];
                sc[(r0 + 8) * 132 + cc + 1] = C[mt][nt][3];
            }
    }
    __syncthreads();
    if (ks == 1) {
#pragma unroll
        for (int mt = 0; mt < 4; mt++)
#pragma unroll
            for (int nt = 0; nt < 8; nt++) {
                int r0 = wm * 64 + mt * 16 + (lane >> 2);
                int cc = wn * 64 + nt * 8 + (lane & 3) * 2;
                sc[r0 * 132 + cc]       += C[mt][nt][0];
                sc[r0 * 132 + cc + 1]   += C[mt][nt][1];
                sc[(r0 + 8) * 132 + cc]     += C[mt][nt][2];
                sc[(r0 + 8) * 132 + cc + 1] += C[mt][nt][3];
            }
    }
    __syncthreads();

    // SiLU(gate)*up -> g_hact; thread t: row t>>1, 32 outputs
    {
        int m = tid >> 1, coff = (tid & 1) * 32;
        size_t orow = (size_t)(base + m) * Hn + h0 + coff;
#pragma unroll
        for (int j = 0; j < 32; j += 4) {
            float v[4];
#pragma unroll
            for (int jj = 0; jj < 4; jj++) {
                float g = sc[m * 132 + coff + j + jj];
                float u = sc[m * 132 + 64 + coff + j + jj];
                v[jj] = g / (1.f + __expf(-g)) * u;
            }
            *(uint2*)(g_hact_h + orow + j) =
                make_uint2(ph_rn(v[0], v[1]), ph_rn(v[2], v[3]));
        }
    }
#undef LDGB1
#undef CPA1
#undef STSB1
#undef COMP1
}

// ---------------------------------------------------------------------------
// GEMM2: out[tok, d0+c] += w * sum_h hact[slot,h] * w2[e,h,d0+c]
// 256 threads, CTA 128x128, BK=64, K-split warp grid (2m x 2n x 2k).
// A = hact plane via cp.async; B = w2 fp32 native [k][n] via LDG+convert,
// ldmatrix.trans read. Epilogue: k-half reduce, then weighted atomicAdd.
// ---------------------------------------------------------------------------
__global__ __launch_bounds__(256, 1) void gemm2_kernel(
    const float* __restrict__ w2,
    float* __restrict__ out) {
    int e = g_tile_expert[blockIdx.x];
    if (e < 0) return;
    int base = g_tile_base[blockIdx.x];
    int d0 = blockIdx.y * 128;

    extern __shared__ char dsm[];
    __shared__ int   s_tok[TILE_M];
    __shared__ float s_w[TILE_M];
    uint32_t raw = smem_u32(dsm);
    uint32_t sb = (raw + 1023u) & ~1023u;
    char* sp = dsm + (sb - raw);

    int tid = threadIdx.x;
    if (tid < TILE_M) {
        s_tok[tid] = g_slot_token[base + tid];
        s_w[tid]   = g_slot_w[base + tid];
    }
    __syncthreads();

    const int warp = tid >> 5, lane = tid & 31;
    const int ks = warp >> 2;
    const int wm = (warp >> 1) & 1, wn = warp & 1;

    // A cp.async: row t>>1, 64B run
    const int arow = tid >> 1;
    const unsigned short* aP =
        g_hact_h + (size_t)(base + arow) * Hn + (tid & 1) * 32;
    uint32_t adst[4];
#pragma unroll
    for (int j = 0; j < 4; j++)
        adst[j] = sw128((uint32_t)arow * 128u + (uint32_t)((tid & 1) * 4 + j) * 16u);

    // B LDG: g 0-7: k-row g*8+warp, lane covers full 512B row
    const float* wP = w2 + ((size_t)e * Hn + warp) * Dn + d0 + lane * 4;
    uint32_t bdst[8];
#pragma unroll
    for (int g = 0; g < 8; g++) {
        uint32_t r = (uint32_t)(g * 8 + warp);
        bdst[g] = sw256(r * 256u + (uint32_t)(lane >> 1) * 16u)
                + (uint32_t)(lane & 1) * 8u;
    }

    // ldmatrix lane offsets
    const uint32_t a_m  = (uint32_t)(lane & 15);
    const uint32_t a_kc = (uint32_t)(lane >> 4);
    const uint32_t t_k  = (uint32_t)((lane & 7) | (((lane >> 3) & 1) << 3));
    const uint32_t t_n8 = (uint32_t)(lane >> 4);

    float C[4][8][4];
#pragma unroll
    for (int i = 0; i < 4; i++)
#pragma unroll
        for (int j = 0; j < 8; j++)
#pragma unroll
            for (int k = 0; k < 4; k++) C[i][j][k] = 0.f;

    float4 Br[8];

#define LDGB2(c) do {                                                       \
    _Pragma("unroll")                                                       \
    for (int g = 0; g < 8; g++)                                             \
        Br[g] = __ldg((const float4*)(wP + ((size_t)(c) * 64 + g * 8) * Dn)); \
} while (0)

#define CPA2(c, st) do {                                                    \
    uint32_t Ab = sb + (st) * 32768u;                                       \
    const unsigned short* as = aP + (c) * 64;                               \
    _Pragma("unroll")                                                       \
    for (int j = 0; j < 4; j++)                                             \
        cpa16(Ab + adst[j], as + j * 8, 16u);                               \
    CP_COMMIT();                                                            \
} while (0)

#define STSB2(st) do {                                                      \
    char* Bh = sp + (st) * 32768 + 16384;                                   \
    _Pragma("unroll")                                                       \
    for (int g = 0; g < 8; g++) {                                           \
        float4 v = Br[g];                                                   \
        *(uint2*)(Bh + bdst[g]) = make_uint2(ph_rn(v.x, v.y), ph_rn(v.z, v.w)); \
    }                                                                       \
} while (0)

#define COMP2(st) do {                                                      \
    uint32_t Au  = sb + (st) * 32768u;                                      \
    uint32_t Bhu = Au + 16384u;                                             \
    _Pragma("unroll")                                                       \
    for (int k16l = 0; k16l < 2; k16l++) {                                  \
        int kk = ks * 2 + k16l;                                             \
        uint32_t aH[4][4];                                                  \
        _Pragma("unroll")                                                   \
        for (int mt = 0; mt < 4; mt++) {                                    \
            uint32_t o = (uint32_t)(wm * 64 + mt * 16 + a_m) * 128u + kk * 32u + a_kc * 16u; \
            ldsm4(aH[mt], Au + sw128(o));                                   \
        }                                                                   \
        _Pragma("unroll")                                                   \
        for (int ng = 0; ng < 4; ng++) {                                    \
            uint32_t o = (kk * 16u + t_k) * 256u                            \
                       + (uint32_t)(wn * 64 + ng * 16) * 2u + t_n8 * 16u;   \
            uint32_t bH[4];                                                 \
            ldsm4t(bH, Bhu + sw256(o));                                     \
            _Pragma("unroll")                                               \
            for (int mt = 0; mt < 4; mt++) {                                \
                mma16816h(C[mt][2 * ng],     aH[mt], bH[0], bH[1]);         \
                mma16816h(C[mt][2 * ng + 1], aH[mt], bH[2], bH[3]);         \
            }                                                               \
        }                                                                   \
    }                                                                       \
} while (0)

    LDGB2(0);
    CPA2(0, 0);
    STSB2(0);
    LDGB2(1);
    for (int c = 0; c < G2_KIT; c++) {
        int st = c & 1;
        CP_WAIT0();
        __syncthreads();
        if (c + 1 < G2_KIT) CPA2(c + 1, st ^ 1);
        COMP2(st);
        if (c + 1 < G2_KIT) STSB2(st ^ 1);
        if (c + 2 < G2_KIT) LDGB2(c + 2);
    }
    __syncthreads();

    // Epilogue: k-half reduce through smem
    float* sc = (float*)sp;
    if (ks == 0) {
#pragma unroll
        for (int mt = 0; mt < 4; mt++)
#pragma unroll
            for (int nt = 0; nt < 8; nt++) {
                int r0 = wm * 64 + mt * 16 + (lane >> 2);
                int cc = wn * 64 + nt * 8 + (lane & 3) * 2;
                sc[r0 * 132 + cc]       = C[mt][nt][0];
                sc[r0 * 132 + cc + 1]   = C[mt][nt][1];
                sc[(r0 + 8) * 132 + cc]     = C[mt][nt][2];
                sc[(r0 + 8) * 132 + cc + 1] = C[mt][nt][3];
            }
    }
    __syncthreads();
    if (ks == 1) {
#pragma unroll
        for (int mt = 0; mt < 4; mt++)
#pragma unroll
            for (int nt = 0; nt < 8; nt++) {
                int r0 = wm * 64 + mt * 16 + (lane >> 2);
                int cc = wn * 64 + nt * 8 + (lane & 3) * 2;
                sc[r0 * 132 + cc]       += C[mt][nt][0];
                sc[r0 * 132 + cc + 1]   += C[mt][nt][1];
                sc[(r0 + 8) * 132 + cc]     += C[mt][nt][2];
                sc[(r0 + 8) * 132 + cc + 1] += C[mt][nt][3];
            }
    }
    __syncthreads();

    // weighted accumulate (K=2 commutative adds -> deterministic)
    {
        int m = tid >> 1, coff = (tid & 1) * 64;
        int tok = s_tok[m];
        if (tok >= 0) {
            float wgt = s_w[m];
            float* dst = out + (size_t)tok * Dn + d0 + coff;
#pragma unroll 8
            for (int j = 0; j < 64; j++)
                atomicAdd(dst + j, wgt * sc[m * 132 + coff + j]);
        }
    }
#undef LDGB2
#undef CPA2
#undef STSB2
#undef COMP2
}

// ---------------------------------------------------------------------------
extern "C" void kernel_launch(void* const* d_in, const int* in_sizes, int n_in,
                              void* d_out, int out_size) {
    const float* x   = (const float*)d_in[0];
    const float* wts = (const float*)d_in[1];
    const int*   sel = (const int*)d_in[2];
    const float* w1  = (const float*)d_in[3];
    const float* w2  = (const float*)d_in[4];
    const float* w3  = (const float*)d_in[5];
    float* out = (float*)d_out;

    cudaFuncSetAttribute(gemm1_kernel,
                         cudaFuncAttributeMaxDynamicSharedMemorySize, SMEM_REQ);
    cudaFuncSetAttribute(gemm2_kernel,
                         cudaFuncAttributeMaxDynamicSharedMemorySize, SMEM_REQ);

    route_kernel<<<1, 1024>>>(sel, wts);
    zero_kernel<<<(Tn * Dn) / 256, 256>>>(out);
    splitx_kernel<<<(Tn * Dn) / 1024, 256>>>((const float4*)x, (Tn * Dn) / 4);
    // tile index fastest: all M-tiles of one weight tile run concurrently,
    // weights stream from DRAM once and reuse via L2.
    gemm1_kernel<<<dim3(MAX_TILES, Hn / 64), 256, SMEM_REQ>>>(w1, w3);
    gemm2_kernel<<<dim3(MAX_TILES, Dn / 128), 256, SMEM_REQ>>>(w2, out);
}

// round 13
// speedup vs baseline: 1.1844x; 1.1844x over previous
#include <cuda_runtime.h>
#include <cuda_fp16.h>
#include <cstdint>

// Problem constants
#define Tn 1024
#define Dn 2048
#define Hn 7168
#define En 8
#define Kn 2
#define Pn (Tn * Kn)                   // 2048 (token,k) pairs
#define TILE_M 128
#define MAX_SLOTS (Pn + En * TILE_M)   // 3072
#define MAX_TILES (Pn / TILE_M + En)   // 24

#define G1_KIT (Dn / 32)               // 64 K-chunks of 32
#define G2_KIT (Hn / 32)               // 224 K-chunks of 32

// Dynamic smem: 2 stages x 32KB + slack (epilogue reuses as 128x132 fp32)
#define SMEM_REQ 68608

// Scratch (device globals; no allocation allowed)
__device__ int   g_slot_token[MAX_SLOTS];
__device__ float g_slot_w[MAX_SLOTS];
__device__ int   g_tile_expert[MAX_TILES];
__device__ int   g_tile_base[MAX_TILES];
// single fp16 plane for the A-side operands
__device__ __align__(16) unsigned short g_x_h[(size_t)Tn * Dn];
__device__ __align__(16) unsigned short g_hact_h[(size_t)MAX_SLOTS * Hn];

// ---------------------------------------------------------------------------
// Helpers
// ---------------------------------------------------------------------------
__device__ __forceinline__ uint32_t smem_u32(const void* p) {
    uint32_t a;
    asm("{ .reg .u64 t; cvta.to.shared.u64 t, %1; cvt.u32.u64 %0, t; }"
        : "=r"(a) : "l"(p));
    return a;
}

__device__ __forceinline__ uint32_t sw128(uint32_t o) {
    return o ^ (((o >> 7) & 7u) << 4);
}
__device__ __forceinline__ uint32_t sw256(uint32_t o) {
    return o ^ (((o >> 8) & 7u) << 4);
}

__device__ __forceinline__ void cpa16(uint32_t dst, const void* src, uint32_t sz) {
    asm volatile("cp.async.cg.shared.global [%0], [%1], 16, %2;"
                 :: "r"(dst), "l"(src), "r"(sz) : "memory");
}
#define CP_COMMIT() asm volatile("cp.async.commit_group;" ::: "memory")
#define CP_WAIT0()  asm volatile("cp.async.wait_group 0;" ::: "memory")

__device__ __forceinline__ void ldsm4(uint32_t* r, uint32_t a) {
    asm volatile("ldmatrix.sync.aligned.m8n8.x4.shared.b16 {%0,%1,%2,%3}, [%4];"
        : "=r"(r[0]), "=r"(r[1]), "=r"(r[2]), "=r"(r[3]) : "r"(a));
}
__device__ __forceinline__ void ldsm4t(uint32_t* r, uint32_t a) {
    asm volatile("ldmatrix.sync.aligned.m8n8.x4.trans.shared.b16 {%0,%1,%2,%3}, [%4];"
        : "=r"(r[0]), "=r"(r[1]), "=r"(r[2]), "=r"(r[3]) : "r"(a));
}
__device__ __forceinline__ void mma16816h(float* c, const uint32_t* a,
                                          uint32_t b0, uint32_t b1) {
    asm volatile(
        "mma.sync.aligned.m16n8k16.row.col.f32.f16.f16.f32 "
        "{%0,%1,%2,%3}, {%4,%5,%6,%7}, {%8,%9}, {%0,%1,%2,%3};"
        : "+f"(c[0]), "+f"(c[1]), "+f"(c[2]), "+f"(c[3])
        : "r"(a[0]), "r"(a[1]), "r"(a[2]), "r"(a[3]), "r"(b0), "r"(b1));
}

__device__ __forceinline__ uint32_t ph_rn(float a, float b) {
    __half2 h = __floats2half2_rn(a, b);
    return *(uint32_t*)&h;
}

// ---------------------------------------------------------------------------
// x convert: fp32 -> fp16 plane (4 MB, ~4us)
// ---------------------------------------------------------------------------
__global__ void splitx_kernel(const float4* __restrict__ src, int n4) {
    int i = blockIdx.x * blockDim.x + threadIdx.x;
    if (i < n4) {
        float4 v = __ldg(src + i);
        ((uint2*)g_x_h)[i] = make_uint2(ph_rn(v.x, v.y), ph_rn(v.z, v.w));
    }
}

// ---------------------------------------------------------------------------
// Routing
// ---------------------------------------------------------------------------
__global__ void route_kernel(const int* __restrict__ sel,
                             const float* __restrict__ wts) {
    __shared__ int s_e[Pn];
    __shared__ int s_cnt[En];
    __shared__ int s_base[En];
    int tid = threadIdx.x;

    if (tid < En) s_cnt[tid] = 0;
    __syncthreads();
    for (int i = tid; i < Pn; i += blockDim.x) {
        int e = sel[i];
        s_e[i] = e;
        atomicAdd(&s_cnt[e], 1);
    }
    __syncthreads();
    if (tid == 0) {
        int base = 0, tile = 0;
        for (int e = 0; e < En; e++) {
            s_base[e] = base;
            int padded = ((s_cnt[e] + TILE_M - 1) / TILE_M) * TILE_M;
            for (int m = 0; m < padded; m += TILE_M) {
                g_tile_expert[tile] = e;
                g_tile_base[tile]   = base + m;
                tile++;
            }
            base += padded;
        }
        for (; tile < MAX_TILES; tile++) g_tile_expert[tile] = -1;
    }
    __syncthreads();
    for (int s = tid; s < MAX_SLOTS; s += blockDim.x) g_slot_token[s] = -1;
    __syncthreads();
    for (int i = tid; i < Pn; i += blockDim.x) {
        int e = s_e[i];
        int rank = 0;
        for (int j = 0; j < i; j++) rank += (s_e[j] == e) ? 1 : 0;
        int slot = s_base[e] + rank;
        g_slot_token[slot] = i / Kn;
        g_slot_w[slot]     = wts[i];
    }
}

__global__ void zero_kernel(float* __restrict__ out) {
    int i = blockIdx.x * blockDim.x + threadIdx.x;
    out[i] = 0.0f;
}

// ---------------------------------------------------------------------------
// GEMM1: hact[slot, h0+c] = silu(x.W1^T) * (x.W3^T)
// Plain fp16. CTA 128x128 (n 0-63 gate / 64-127 up), BK=32, 4 warps 64x64.
// B staging: thread converts a 32B fp32 run -> one 16B STS.128.
// ---------------------------------------------------------------------------
__global__ __launch_bounds__(128, 2) void gemm1_kernel(
    const float* __restrict__ w1,
    const float* __restrict__ w3) {
    int e = g_tile_expert[blockIdx.x];
    if (e < 0) return;
    int base = g_tile_base[blockIdx.x];
    int h0 = blockIdx.y * 64;

    extern __shared__ char dsm[];
    __shared__ int s_tok[TILE_M];
    uint32_t raw = smem_u32(dsm);
    uint32_t sb = (raw + 1023u) & ~1023u;
    char* sp = dsm + (sb - raw);

    int tid = threadIdx.x;
    s_tok[tid] = g_slot_token[base + tid];
    __syncthreads();

    const int warp = tid >> 5, lane = tid & 31;
    const int wm = warp & 1, wn = warp >> 1;   // 2m x 2n, warp tile 64x64

    // A: thread t serves rows g*32+(t>>2), granule t&3 (16B of a 64B row run)
    const unsigned short* aP[4];
    uint32_t avz[4], adst[4];
#pragma unroll
    for (int g = 0; g < 4; g++) {
        int r = g * 32 + (tid >> 2);
        int tk = s_tok[r];
        aP[g]  = g_x_h + (size_t)(tk < 0 ? 0 : tk) * Dn + (tid & 3) * 8;
        avz[g] = (tk >= 0) ? 16u : 0u;
        adst[g] = sw128((uint32_t)r * 128u + (uint32_t)(tid & 3) * 16u);
    }

    // B: thread t serves rows g*32+(t>>2) (g0,1 w1 / g2,3 w3), seg t&3 = 32B
    const int brow = tid >> 2, bseg = tid & 3;
    const float* b1P = w1 + ((size_t)e * Hn + h0 + brow) * Dn + bseg * 8;
    const float* b3P = w3 + ((size_t)e * Hn + h0 + brow) * Dn + bseg * 8;
    uint32_t bdst[4];
#pragma unroll
    for (int g = 0; g < 4; g++) {
        uint32_t r = (uint32_t)(g * 32 + brow);
        bdst[g] = sw128(r * 128u + (uint32_t)bseg * 16u);
    }

    // ldmatrix lane offsets
    const uint32_t a_m  = (uint32_t)(lane & 15);
    const uint32_t a_kc = (uint32_t)(lane >> 4);
    const uint32_t b_n  = (uint32_t)((lane & 7) | ((lane >> 4) << 3));
    const uint32_t b_kc = (uint32_t)((lane >> 3) & 1);

    float C[4][8][4];
#pragma unroll
    for (int i = 0; i < 4; i++)
#pragma unroll
        for (int j = 0; j < 8; j++)
#pragma unroll
            for (int k = 0; k < 4; k++) C[i][j][k] = 0.f;

    float4 Br[8];

#define LDGB1(c) do {                                                       \
    _Pragma("unroll")                                                       \
    for (int g = 0; g < 4; g++) {                                           \
        const float* q = (g < 2 ? b1P + (size_t)g * 32 * Dn                 \
                                : b3P + (size_t)(g - 2) * 32 * Dn) + (c) * 32; \
        Br[2 * g]     = __ldg((const float4*)q);                            \
        Br[2 * g + 1] = __ldg((const float4*)q + 1);                        \
    }                                                                       \
} while (0)

#define CPA1(c, st) do {                                                    \
    uint32_t Ab = sb + (st) * 32768u;                                       \
    _Pragma("unroll")                                                       \
    for (int g = 0; g < 4; g++)                                             \
        cpa16(Ab + adst[g], aP[g] + (c) * 32, avz[g]);                      \
    CP_COMMIT();                                                            \
} while (0)

#define STSB1(st) do {                                                      \
    char* Bb = sp + (st) * 32768 + 16384;                                   \
    _Pragma("unroll")                                                       \
    for (int g = 0; g < 4; g++) {                                           \
        float4 v0 = Br[2 * g], v1 = Br[2 * g + 1];                          \
        uint4 h = make_uint4(ph_rn(v0.x, v0.y), ph_rn(v0.z, v0.w),          \
                             ph_rn(v1.x, v1.y), ph_rn(v1.z, v1.w));         \
        *(uint4*)(Bb + bdst[g]) = h;                                        \
    }                                                                       \
} while (0)

#define COMP1(st) do {                                                      \
    uint32_t Au = sb + (st) * 32768u;                                       \
    uint32_t Bu = Au + 16384u;                                              \
    _Pragma("unroll")                                                       \
    for (int k16 = 0; k16 < 2; k16++) {                                     \
        uint32_t aH[4][4];                                                  \
        _Pragma("unroll")                                                   \
        for (int mt = 0; mt < 4; mt++) {                                    \
            uint32_t o = (uint32_t)(wm * 64 + mt * 16 + a_m) * 128u + k16 * 32u + a_kc * 16u; \
            ldsm4(aH[mt], Au + sw128(o));                                   \
        }                                                                   \
        _Pragma("unroll")                                                   \
        for (int ng = 0; ng < 4; ng++) {                                    \
            uint32_t o = (uint32_t)(wn * 64 + ng * 16 + b_n) * 128u + k16 * 32u + b_kc * 16u; \
            uint32_t bH[4];                                                 \
            ldsm4(bH, Bu + sw128(o));                                       \
            _Pragma("unroll")                                               \
            for (int mt = 0; mt < 4; mt++) {                                \
                mma16816h(C[mt][2 * ng],     aH[mt], bH[0], bH[1]);         \
                mma16816h(C[mt][2 * ng + 1], aH[mt], bH[2], bH[3]);         \
            }                                                               \
        }                                                                   \
    }                                                                       \
} while (0)

    LDGB1(0);
    CPA1(0, 0);
    STSB1(0);
    LDGB1(1);
    for (int c = 0; c < G1_KIT; c++) {
        int st = c & 1;
        CP_WAIT0();
        __syncthreads();
        if (c + 1 < G1_KIT) CPA1(c + 1, st ^ 1);
        COMP1(st);
        if (c + 1 < G1_KIT) STSB1(st ^ 1);
        if (c + 2 < G1_KIT) LDGB1(c + 2);
    }
    __syncthreads();

    // C -> smem fp32 [128][132]
    float* sc = (float*)sp;
#pragma unroll
    for (int mt = 0; mt < 4; mt++)
#pragma unroll
        for (int nt = 0; nt < 8; nt++) {
            int r0 = wm * 64 + mt * 16 + (lane >> 2);
            int cc = wn * 64 + nt * 8 + (lane & 3) * 2;
            sc[r0 * 132 + cc]       = C[mt][nt][0];
            sc[r0 * 132 + cc + 1]   = C[mt][nt][1];
            sc[(r0 + 8) * 132 + cc]     = C[mt][nt][2];
            sc[(r0 + 8) * 132 + cc + 1] = C[mt][nt][3];
        }
    __syncthreads();

    // SiLU(gate)*up -> g_hact fp16 plane; thread t owns row t (64 outputs)
    {
        size_t orow = (size_t)(base + tid) * Hn + h0;
#pragma unroll
        for (int j = 0; j < 64; j += 4) {
            float v[4];
#pragma unroll
            for (int jj = 0; jj < 4; jj++) {
                float g = sc[tid * 132 + j + jj];
                float u = sc[tid * 132 + 64 + j + jj];
                v[jj] = g / (1.f + __expf(-g)) * u;
            }
            *(uint2*)(g_hact_h + orow + j) =
                make_uint2(ph_rn(v[0], v[1]), ph_rn(v[2], v[3]));
        }
    }
#undef LDGB1
#undef CPA1
#undef STSB1
#undef COMP1
}

// ---------------------------------------------------------------------------
// GEMM2: out[tok, d0+c] += w * sum_h hact[slot,h] * w2[e,h,d0+c]
// Plain fp16. CTA 128x128, 4 warps 64x64, 2-stage pipeline.
// B staging: thread converts a 32B fp32 run -> one 16B STS.128.
// ---------------------------------------------------------------------------
__global__ __launch_bounds__(128, 2) void gemm2_kernel(
    const float* __restrict__ w2,
    float* __restrict__ out) {
    int e = g_tile_expert[blockIdx.x];
    if (e < 0) return;
    int base = g_tile_base[blockIdx.x];
    int d0 = blockIdx.y * 128;

    extern __shared__ char dsm[];
    __shared__ int   s_tok[TILE_M];
    __shared__ float s_w[TILE_M];
    uint32_t raw = smem_u32(dsm);
    uint32_t sb = (raw + 1023u) & ~1023u;
    char* sp = dsm + (sb - raw);

    int tid = threadIdx.x;
    s_tok[tid] = g_slot_token[base + tid];
    s_w[tid]   = g_slot_w[base + tid];
    __syncthreads();

    const int warp = tid >> 5, lane = tid & 31;
    const int wm = warp & 1, wn = warp >> 1;

    // A: thread t serves rows g*32+(t>>2), granule t&3
    const unsigned short* aP[4];
    uint32_t adst[4];
#pragma unroll
    for (int g = 0; g < 4; g++) {
        int r = g * 32 + (tid >> 2);
        aP[g]   = g_hact_h + (size_t)(base + r) * Hn + (tid & 3) * 8;
        adst[g] = sw128((uint32_t)r * 128u + (uint32_t)(tid & 3) * 16u);
    }

    // B: thread t serves k-rows g*8+(t>>4), seg t&15 = 32B of the 512B row
    const int brow = tid >> 4, bseg = tid & 15;
    const float* wP = w2 + ((size_t)e * Hn + brow) * Dn + d0 + bseg * 8;
    uint32_t bdst[4];
#pragma unroll
    for (int g = 0; g < 4; g++) {
        uint32_t r = (uint32_t)(g * 8 + brow);
        bdst[g] = sw256(r * 256u + (uint32_t)bseg * 16u);
    }

    // ldmatrix lane offsets
    const uint32_t a_m  = (uint32_t)(lane & 15);
    const uint32_t a_kc = (uint32_t)(lane >> 4);
    const uint32_t t_k  = (uint32_t)((lane & 7) | (((lane >> 3) & 1) << 3));
    const uint32_t t_n8 = (uint32_t)(lane >> 4);

    float C[4][8][4];
#pragma unroll
    for (int i = 0; i < 4; i++)
#pragma unroll
        for (int j = 0; j < 8; j++)
#pragma unroll
            for (int k = 0; k < 4; k++) C[i][j][k] = 0.f;

    float4 Br[8];

#define LDGB2(c) do {                                                       \
    _Pragma("unroll")                                                       \
    for (int g = 0; g < 4; g++) {                                           \
        const float* q = wP + ((size_t)(c) * 32 + g * 8) * Dn;              \
        Br[2 * g]     = __ldg((const float4*)q);                            \
        Br[2 * g + 1] = __ldg((const float4*)q + 1);                        \
    }                                                                       \
} while (0)

#define CPA2(c, st) do {                                                    \
    uint32_t Ab = sb + (st) * 32768u;                                       \
    _Pragma("unroll")                                                       \
    for (int g = 0; g < 4; g++)                                             \
        cpa16(Ab + adst[g], aP[g] + (c) * 32, 16u);                         \
    CP_COMMIT();                                                            \
} while (0)

#define STSB2(st) do {                                                      \
    char* Bh = sp + (st) * 32768 + 16384;                                   \
    _Pragma("unroll")                                                       \
    for (int g = 0; g < 4; g++) {                                           \
        float4 v0 = Br[2 * g], v1 = Br[2 * g + 1];                          \
        uint4 h = make_uint4(ph_rn(v0.x, v0.y), ph_rn(v0.z, v0.w),          \
                             ph_rn(v1.x, v1.y), ph_rn(v1.z, v1.w));         \
        *(uint4*)(Bh + bdst[g]) = h;                                        \
    }                                                                       \
} while (0)

#define COMP2(st) do {                                                      \
    uint32_t Au  = sb + (st) * 32768u;                                      \
    uint32_t Bhu = Au + 16384u;                                             \
    _Pragma("unroll")                                                       \
    for (int k16 = 0; k16 < 2; k16++) {                                     \
        uint32_t aH[4][4];                                                  \
        _Pragma("unroll")                                                   \
        for (int mt = 0; mt < 4; mt++) {                                    \
            uint32_t o = (uint32_t)(wm * 64 + mt * 16 + a_m) * 128u + k16 * 32u + a_kc * 16u; \
            ldsm4(aH[mt], Au + sw128(o));                                   \
        }                                                                   \
        _Pragma("unroll")                                                   \
        for (int ng = 0; ng < 4; ng++) {                                    \
            uint32_t o = (k16 * 16u + t_k) * 256u                           \
                       + (uint32_t)(wn * 64 + ng * 16) * 2u + t_n8 * 16u;   \
            uint32_t bH[4];                                                 \
            ldsm4t(bH, Bhu + sw256(o));                                     \
            _Pragma("unroll")                                               \
            for (int mt = 0; mt < 4; mt++) {                                \
                mma16816h(C[mt][2 * ng],     aH[mt], bH[0], bH[1]);         \
                mma16816h(C[mt][2 * ng + 1], aH[mt], bH[2], bH[3]);         \
            }                                                               \
        }                                                                   \
    }                                                                       \
} while (0)

    LDGB2(0);
    CPA2(0, 0);
    STSB2(0);
    LDGB2(1);
    for (int c = 0; c < G2_KIT; c++) {
        int st = c & 1;
        CP_WAIT0();
        __syncthreads();
        if (c + 1 < G2_KIT) CPA2(c + 1, st ^ 1);
        COMP2(st);
        if (c + 1 < G2_KIT) STSB2(st ^ 1);
        if (c + 2 < G2_KIT) LDGB2(c + 2);
    }
    __syncthreads();

    // C -> smem fp32 [128][132]
    float* sc = (float*)sp;
#pragma unroll
    for (int mt = 0; mt < 4; mt++)
#pragma unroll
        for (int nt = 0; nt < 8; nt++) {
            int r0 = wm * 64 + mt * 16 + (lane >> 2);
            int cc = wn * 64 + nt * 8 + (lane & 3) * 2;
            sc[r0 * 132 + cc]       = C[mt][nt][0];
            sc[r0 * 132 + cc + 1]   = C[mt][nt][1];
            sc[(r0 + 8) * 132 + cc]     = C[mt][nt][2];
            sc[(r0 + 8) * 132 + cc + 1] = C[mt][nt][3];
        }
    __syncthreads();

    // weighted accumulate (K=2 commutative adds -> deterministic)
    {
        int tok = s_tok[tid];
        if (tok >= 0) {
            float wgt = s_w[tid];
            float* dst = out + (size_t)tok * Dn + d0;
#pragma unroll 8
            for (int j = 0; j < 128; j++)
                atomicAdd(dst + j, wgt * sc[tid * 132 + j]);
        }
    }
#undef LDGB2
#undef CPA2
#undef STSB2
#undef COMP2
}

// ---------------------------------------------------------------------------
extern "C" void kernel_launch(void* const* d_in, const int* in_sizes, int n_in,
                              void* d_out, int out_size) {
    const float* x   = (const float*)d_in[0];
    const float* wts = (const float*)d_in[1];
    const int*   sel = (const int*)d_in[2];
    const float* w1  = (const float*)d_in[3];
    const float* w2  = (const float*)d_in[4];
    const float* w3  = (const float*)d_in[5];
    float* out = (float*)d_out;

    cudaFuncSetAttribute(gemm1_kernel,
                         cudaFuncAttributeMaxDynamicSharedMemorySize, SMEM_REQ);
    cudaFuncSetAttribute(gemm2_kernel,
                         cudaFuncAttributeMaxDynamicSharedMemorySize, SMEM_REQ);

    route_kernel<<<1, 1024>>>(sel, wts);
    zero_kernel<<<(Tn * Dn) / 256, 256>>>(out);
    splitx_kernel<<<(Tn * Dn) / 1024, 256>>>((const float4*)x, (Tn * Dn) / 4);
    // tile index fastest: all M-tiles of one weight tile run concurrently,
    // weights stream from DRAM once and reuse via L2.
    gemm1_kernel<<<dim3(MAX_TILES, Hn / 64), 128, SMEM_REQ>>>(w1, w3);
    gemm2_kernel<<<dim3(MAX_TILES, Dn / 128), 128, SMEM_REQ>>>(w2, out);
}

// round 14
// speedup vs baseline: 1.2275x; 1.0364x over previous
#include <cuda_runtime.h>
#include <cuda_fp16.h>
#include <cstdint>

// Problem constants
#define Tn 1024
#define Dn 2048
#define Hn 7168
#define En 8
#define Kn 2
#define Pn (Tn * Kn)                   // 2048 (token,k) pairs
#define TILE_M 128
#define MAX_SLOTS (Pn + En * TILE_M)   // 3072
#define MAX_TILES (Pn / TILE_M + En)   // 24

#define G1_KIT (Dn / 32)               // 64 K-chunks of 32
#define G2_HALF (Hn / 2)               // 3584
#define G2_KIT (G2_HALF / 32)          // 112 K-chunks per half

// Dynamic smem: 2 stages x 32KB + slack (epilogue reuses as 128x132 fp32)
#define SMEM_REQ 68608

// Scratch (device globals; no allocation allowed)
__device__ int   g_slot_token[MAX_SLOTS];
__device__ float g_slot_w[MAX_SLOTS];
__device__ int   g_tile_expert[MAX_TILES];
__device__ int   g_tile_base[MAX_TILES];
__device__ int   g_pair_slot[Pn];
// single fp16 plane for the A-side operands
__device__ __align__(16) unsigned short g_x_h[(size_t)Tn * Dn];
__device__ __align__(16) unsigned short g_hact_h[(size_t)MAX_SLOTS * Hn];
// per-half, per-slot gemm2 partials (~50 MB)
__device__ __align__(16) float g_y[(size_t)2 * MAX_SLOTS * Dn];

// ---------------------------------------------------------------------------
// Helpers
// ---------------------------------------------------------------------------
__device__ __forceinline__ uint32_t smem_u32(const void* p) {
    uint32_t a;
    asm("{ .reg .u64 t; cvta.to.shared.u64 t, %1; cvt.u32.u64 %0, t; }"
        : "=r"(a) : "l"(p));
    return a;
}

__device__ __forceinline__ uint32_t sw128(uint32_t o) {
    return o ^ (((o >> 7) & 7u) << 4);
}
__device__ __forceinline__ uint32_t sw256(uint32_t o) {
    return o ^ (((o >> 8) & 7u) << 4);
}

__device__ __forceinline__ void cpa16(uint32_t dst, const void* src, uint32_t sz) {
    asm volatile("cp.async.cg.shared.global [%0], [%1], 16, %2;"
                 :: "r"(dst), "l"(src), "r"(sz) : "memory");
}
#define CP_COMMIT() asm volatile("cp.async.commit_group;" ::: "memory")
#define CP_WAIT0()  asm volatile("cp.async.wait_group 0;" ::: "memory")

__device__ __forceinline__ void ldsm4(uint32_t* r, uint32_t a) {
    asm volatile("ldmatrix.sync.aligned.m8n8.x4.shared.b16 {%0,%1,%2,%3}, [%4];"
        : "=r"(r[0]), "=r"(r[1]), "=r"(r[2]), "=r"(r[3]) : "r"(a));
}
__device__ __forceinline__ void ldsm4t(uint32_t* r, uint32_t a) {
    asm volatile("ldmatrix.sync.aligned.m8n8.x4.trans.shared.b16 {%0,%1,%2,%3}, [%4];"
        : "=r"(r[0]), "=r"(r[1]), "=r"(r[2]), "=r"(r[3]) : "r"(a));
}
__device__ __forceinline__ void mma16816h(float* c, const uint32_t* a,
                                          uint32_t b0, uint32_t b1) {
    asm volatile(
        "mma.sync.aligned.m16n8k16.row.col.f32.f16.f16.f32 "
        "{%0,%1,%2,%3}, {%4,%5,%6,%7}, {%8,%9}, {%0,%1,%2,%3};"
        : "+f"(c[0]), "+f"(c[1]), "+f"(c[2]), "+f"(c[3])
        : "r"(a[0]), "r"(a[1]), "r"(a[2]), "r"(a[3]), "r"(b0), "r"(b1));
}

__device__ __forceinline__ uint32_t ph_rn(float a, float b) {
    __half2 h = __floats2half2_rn(a, b);
    return *(uint32_t*)&h;
}

// ---------------------------------------------------------------------------
// x convert: fp32 -> fp16 plane (4 MB, ~4us)
// ---------------------------------------------------------------------------
__global__ void splitx_kernel(const float4* __restrict__ src, int n4) {
    int i = blockIdx.x * blockDim.x + threadIdx.x;
    if (i < n4) {
        float4 v = __ldg(src + i);
        ((uint2*)g_x_h)[i] = make_uint2(ph_rn(v.x, v.y), ph_rn(v.z, v.w));
    }
}

// ---------------------------------------------------------------------------
// Routing (also records pair -> slot)
// ---------------------------------------------------------------------------
__global__ void route_kernel(const int* __restrict__ sel,
                             const float* __restrict__ wts) {
    __shared__ int s_e[Pn];
    __shared__ int s_cnt[En];
    __shared__ int s_base[En];
    int tid = threadIdx.x;

    if (tid < En) s_cnt[tid] = 0;
    __syncthreads();
    for (int i = tid; i < Pn; i += blockDim.x) {
        int e = sel[i];
        s_e[i] = e;
        atomicAdd(&s_cnt[e], 1);
    }
    __syncthreads();
    if (tid == 0) {
        int base = 0, tile = 0;
        for (int e = 0; e < En; e++) {
            s_base[e] = base;
            int padded = ((s_cnt[e] + TILE_M - 1) / TILE_M) * TILE_M;
            for (int m = 0; m < padded; m += TILE_M) {
                g_tile_expert[tile] = e;
                g_tile_base[tile]   = base + m;
                tile++;
            }
            base += padded;
        }
        for (; tile < MAX_TILES; tile++) g_tile_expert[tile] = -1;
    }
    __syncthreads();
    for (int s = tid; s < MAX_SLOTS; s += blockDim.x) g_slot_token[s] = -1;
    __syncthreads();
    for (int i = tid; i < Pn; i += blockDim.x) {
        int e = s_e[i];
        int rank = 0;
        for (int j = 0; j < i; j++) rank += (s_e[j] == e) ? 1 : 0;
        int slot = s_base[e] + rank;
        g_slot_token[slot] = i / Kn;
        g_slot_w[slot]     = wts[i];
        g_pair_slot[i]     = slot;
    }
}

// ---------------------------------------------------------------------------
// Combine: out[t,d] = w0*(y0h0+y0h1) + w1*(y1h0+y1h1)   (fixed order, determ.)
// ---------------------------------------------------------------------------
__global__ void combine_kernel(const float* __restrict__ wts,
                               float* __restrict__ out) {
    int i = blockIdx.x * blockDim.x + threadIdx.x;   // over Tn*Dn/4
    int tok = i >> 9;                                 // Dn/4 = 512
    int d4 = i & 511;
    int s0 = g_pair_slot[2 * tok], s1 = g_pair_slot[2 * tok + 1];
    float w0 = wts[2 * tok], w1 = wts[2 * tok + 1];
    const float4* y = (const float4*)g_y;
    const size_t n4 = Dn / 4;
    float4 a = y[(size_t)s0 * n4 + d4];
    float4 b = y[((size_t)MAX_SLOTS + s0) * n4 + d4];
    float4 c = y[(size_t)s1 * n4 + d4];
    float4 d = y[((size_t)MAX_SLOTS + s1) * n4 + d4];
    float4 o;
    o.x = w0 * (a.x + b.x) + w1 * (c.x + d.x);
    o.y = w0 * (a.y + b.y) + w1 * (c.y + d.y);
    o.z = w0 * (a.z + b.z) + w1 * (c.z + d.z);
    o.w = w0 * (a.w + b.w) + w1 * (c.w + d.w);
    ((float4*)out)[i] = o;
}

// ---------------------------------------------------------------------------
// GEMM1: hact[slot, h0+c] = silu(x.W1^T) * (x.W3^T)   [R11 verbatim]
// Plain fp16. CTA 128x128 (n 0-63 gate / 64-127 up), BK=32, 4 warps 64x64.
// ---------------------------------------------------------------------------
__global__ __launch_bounds__(128, 2) void gemm1_kernel(
    const float* __restrict__ w1,
    const float* __restrict__ w3) {
    int e = g_tile_expert[blockIdx.x];
    if (e < 0) return;
    int base = g_tile_base[blockIdx.x];
    int h0 = blockIdx.y * 64;

    extern __shared__ char dsm[];
    __shared__ int s_tok[TILE_M];
    uint32_t raw = smem_u32(dsm);
    uint32_t sb = (raw + 1023u) & ~1023u;
    char* sp = dsm + (sb - raw);

    int tid = threadIdx.x;
    s_tok[tid] = g_slot_token[base + tid];
    __syncthreads();

    const int warp = tid >> 5, lane = tid & 31;
    const int wm = warp & 1, wn = warp >> 1;   // 2m x 2n, warp tile 64x64

    // A: thread t serves rows g*32+(t>>2), granule t&3 (16B of a 64B row run)
    const unsigned short* aP[4];
    uint32_t avz[4], adst[4];
#pragma unroll
    for (int g = 0; g < 4; g++) {
        int r = g * 32 + (tid >> 2);
        int tk = s_tok[r];
        aP[g]  = g_x_h + (size_t)(tk < 0 ? 0 : tk) * Dn + (tid & 3) * 8;
        avz[g] = (tk >= 0) ? 16u : 0u;
        adst[g] = sw128((uint32_t)r * 128u + (uint32_t)(tid & 3) * 16u);
    }

    // B: thread t serves rows g*16+(t>>3), seg t&7 (16B fp32 -> 8B fp16)
    const float* b1P = w1 + ((size_t)e * Hn + h0 + (tid >> 3)) * Dn + (tid & 7) * 4;
    const float* b3P = w3 + ((size_t)e * Hn + h0 + (tid >> 3)) * Dn + (tid & 7) * 4;
    uint32_t bdst[8];
#pragma unroll
    for (int g = 0; g < 8; g++) {
        uint32_t r = (uint32_t)(g * 16 + (tid >> 3));
        bdst[g] = sw128(r * 128u + (uint32_t)((tid & 7) >> 1) * 16u)
                + (uint32_t)((tid & 7) & 1) * 8u;
    }

    // ldmatrix lane offsets
    const uint32_t a_m  = (uint32_t)(lane & 15);
    const uint32_t a_kc = (uint32_t)(lane >> 4);
    const uint32_t b_n  = (uint32_t)((lane & 7) | ((lane >> 4) << 3));
    const uint32_t b_kc = (uint32_t)((lane >> 3) & 1);

    float C[4][8][4];
#pragma unroll
    for (int i = 0; i < 4; i++)
#pragma unroll
        for (int j = 0; j < 8; j++)
#pragma unroll
            for (int k = 0; k < 4; k++) C[i][j][k] = 0.f;

    float4 Br[8];

#define LDGB1(c) do {                                                       \
    _Pragma("unroll")                                                       \
    for (int g = 0; g < 4; g++)                                             \
        Br[g] = __ldg((const float4*)(b1P + (size_t)g * 16 * Dn + (c) * 32)); \
    _Pragma("unroll")                                                       \
    for (int g = 4; g < 8; g++)                                             \
        Br[g] = __ldg((const float4*)(b3P + (size_t)(g - 4) * 16 * Dn + (c) * 32)); \
} while (0)

#define CPA1(c, st) do {                                                    \
    uint32_t Ab = sb + (st) * 32768u;                                       \
    _Pragma("unroll")                                                       \
    for (int g = 0; g < 4; g++)                                             \
        cpa16(Ab + adst[g], aP[g] + (c) * 32, avz[g]);                      \
    CP_COMMIT();                                                            \
} while (0)

#define STSB1(st) do {                                                      \
    char* Bb = sp + (st) * 32768 + 16384;                                   \
    _Pragma("unroll")                                                       \
    for (int g = 0; g < 8; g++) {                                           \
        float4 v = Br[g];                                                   \
        *(uint2*)(Bb + bdst[g]) = make_uint2(ph_rn(v.x, v.y), ph_rn(v.z, v.w)); \
    }                                                                       \
} while (0)

#define COMP1(st) do {                                                      \
    uint32_t Au = sb + (st) * 32768u;                                       \
    uint32_t Bu = Au + 16384u;                                              \
    _Pragma("unroll")                                                       \
    for (int k16 = 0; k16 < 2; k16++) {                                     \
        uint32_t aH[4][4];                                                  \
        _Pragma("unroll")                                                   \
        for (int mt = 0; mt < 4; mt++) {                                    \
            uint32_t o = (uint32_t)(wm * 64 + mt * 16 + a_m) * 128u + k16 * 32u + a_kc * 16u; \
            ldsm4(aH[mt], Au + sw128(o));                                   \
        }                                                                   \
        _Pragma("unroll")                                                   \
        for (int ng = 0; ng < 4; ng++) {                                    \
            uint32_t o = (uint32_t)(wn * 64 + ng * 16 + b_n) * 128u + k16 * 32u + b_kc * 16u; \
            uint32_t bH[4];                                                 \
            ldsm4(bH, Bu + sw128(o));                                       \
            _Pragma("unroll")                                               \
            for (int mt = 0; mt < 4; mt++) {                                \
                mma16816h(C[mt][2 * ng],     aH[mt], bH[0], bH[1]);         \
                mma16816h(C[mt][2 * ng + 1], aH[mt], bH[2], bH[3]);         \
            }                                                               \
        }                                                                   \
    }                                                                       \
} while (0)

    LDGB1(0);
    CPA1(0, 0);
    STSB1(0);
    LDGB1(1);
    for (int c = 0; c < G1_KIT; c++) {
        int st = c & 1;
        CP_WAIT0();
        __syncthreads();
        if (c + 1 < G1_KIT) CPA1(c + 1, st ^ 1);
        COMP1(st);
        if (c + 1 < G1_KIT) STSB1(st ^ 1);
        if (c + 2 < G1_KIT) LDGB1(c + 2);
    }
    __syncthreads();

    // C -> smem fp32 [128][132]
    float* sc = (float*)sp;
#pragma unroll
    for (int mt = 0; mt < 4; mt++)
#pragma unroll
        for (int nt = 0; nt < 8; nt++) {
            int r0 = wm * 64 + mt * 16 + (lane >> 2);
            int cc = wn * 64 + nt * 8 + (lane & 3) * 2;
            sc[r0 * 132 + cc]       = C[mt][nt][0];
            sc[r0 * 132 + cc + 1]   = C[mt][nt][1];
            sc[(r0 + 8) * 132 + cc]     = C[mt][nt][2];
            sc[(r0 + 8) * 132 + cc + 1] = C[mt][nt][3];
        }
    __syncthreads();

    // SiLU(gate)*up -> g_hact fp16 plane; thread t owns row t (64 outputs)
    {
        size_t orow = (size_t)(base + tid) * Hn + h0;
#pragma unroll
        for (int j = 0; j < 64; j += 4) {
            float v[4];
#pragma unroll
            for (int jj = 0; jj < 4; jj++) {
                float g = sc[tid * 132 + j + jj];
                float u = sc[tid * 132 + 64 + j + jj];
                v[jj] = g / (1.f + __expf(-g)) * u;
            }
            *(uint2*)(g_hact_h + orow + j) =
                make_uint2(ph_rn(v[0], v[1]), ph_rn(v[2], v[3]));
        }
    }
#undef LDGB1
#undef CPA1
#undef STSB1
#undef COMP1
}

// ---------------------------------------------------------------------------
// GEMM2 (K-split x2): g_y[half][slot, d0+c] = sum_{h in half} hact*w2
// Plain fp16, CTA 128x128, 4 warps 64x64, 2-stage pipeline, STG epilogue.
// ---------------------------------------------------------------------------
__global__ __launch_bounds__(128, 2) void gemm2_kernel(
    const float* __restrict__ w2) {
    int e = g_tile_expert[blockIdx.x];
    if (e < 0) return;
    int base = g_tile_base[blockIdx.x];
    int d0 = blockIdx.y * 128;
    int kh = blockIdx.z;
    const int hoff = kh * G2_HALF;

    extern __shared__ char dsm[];
    uint32_t raw = smem_u32(dsm);
    uint32_t sb = (raw + 1023u) & ~1023u;
    char* sp = dsm + (sb - raw);

    int tid = threadIdx.x;
    const int warp = tid >> 5, lane = tid & 31;
    const int wm = warp & 1, wn = warp >> 1;

    // A: thread t serves rows g*32+(t>>2), granule t&3
    const unsigned short* aP[4];
    uint32_t adst[4];
#pragma unroll
    for (int g = 0; g < 4; g++) {
        int r = g * 32 + (tid >> 2);
        aP[g]   = g_hact_h + (size_t)(base + r) * Hn + hoff + (tid & 3) * 8;
        adst[g] = sw128((uint32_t)r * 128u + (uint32_t)(tid & 3) * 16u);
    }

    // B: warp reads k-row g*4+warp, lane covers seg=lane (16B fp32 -> 8B)
    const float* wP = w2 + ((size_t)e * Hn + hoff + warp) * Dn + d0 + lane * 4;
    uint32_t bdst[8];
#pragma unroll
    for (int g = 0; g < 8; g++) {
        uint32_t r = (uint32_t)(g * 4 + warp);
        bdst[g] = sw256(r * 256u + (uint32_t)(lane >> 1) * 16u)
                + (uint32_t)(lane & 1) * 8u;
    }

    // ldmatrix lane offsets
    const uint32_t a_m  = (uint32_t)(lane & 15);
    const uint32_t a_kc = (uint32_t)(lane >> 4);
    const uint32_t t_k  = (uint32_t)((lane & 7) | (((lane >> 3) & 1) << 3));
    const uint32_t t_n8 = (uint32_t)(lane >> 4);

    float C[4][8][4];
#pragma unroll
    for (int i = 0; i < 4; i++)
#pragma unroll
        for (int j = 0; j < 8; j++)
#pragma unroll
            for (int k = 0; k < 4; k++) C[i][j][k] = 0.f;

    float4 Br[8];

#define LDGB2(c) do {                                                       \
    _Pragma("unroll")                                                       \
    for (int g = 0; g < 8; g++)                                             \
        Br[g] = __ldg((const float4*)(wP + ((size_t)(c) * 32 + g * 4) * Dn)); \
} while (0)

#define CPA2(c, st) do {                                                    \
    uint32_t Ab = sb + (st) * 32768u;                                       \
    _Pragma("unroll")                                                       \
    for (int g = 0; g < 4; g++)                                             \
        cpa16(Ab + adst[g], aP[g] + (c) * 32, 16u);                         \
    CP_COMMIT();                                                            \
} while (0)

#define STSB2(st) do {                                                      \
    char* Bh = sp + (st) * 32768 + 16384;                                   \
    _Pragma("unroll")                                                       \
    for (int g = 0; g < 8; g++) {                                           \
        float4 v = Br[g];                                                   \
        *(uint2*)(Bh + bdst[g]) = make_uint2(ph_rn(v.x, v.y), ph_rn(v.z, v.w)); \
    }                                                                       \
} while (0)

#define COMP2(st) do {                                                      \
    uint32_t Au  = sb + (st) * 32768u;                                      \
    uint32_t Bhu = Au + 16384u;                                             \
    _Pragma("unroll")                                                       \
    for (int k16 = 0; k16 < 2; k16++) {                                     \
        uint32_t aH[4][4];                                                  \
        _Pragma("unroll")                                                   \
        for (int mt = 0; mt < 4; mt++) {                                    \
            uint32_t o = (uint32_t)(wm * 64 + mt * 16 + a_m) * 128u + k16 * 32u + a_kc * 16u; \
            ldsm4(aH[mt], Au + sw128(o));                                   \
        }                                                                   \
        _Pragma("unroll")                                                   \
        for (int ng = 0; ng < 4; ng++) {                                    \
            uint32_t o = (k16 * 16u + t_k) * 256u                           \
                       + (uint32_t)(wn * 64 + ng * 16) * 2u + t_n8 * 16u;   \
            uint32_t bH[4];                                                 \
            ldsm4t(bH, Bhu + sw256(o));                                     \
            _Pragma("unroll")                                               \
            for (int mt = 0; mt < 4; mt++) {                                \
                mma16816h(C[mt][2 * ng],     aH[mt], bH[0], bH[1]);         \
                mma16816h(C[mt][2 * ng + 1], aH[mt], bH[2], bH[3]);         \
            }                                                               \
        }                                                                   \
    }                                                                       \
} while (0)

    LDGB2(0);
    CPA2(0, 0);
    STSB2(0);
    LDGB2(1);
    for (int c = 0; c < G2_KIT; c++) {
        int st = c & 1;
        CP_WAIT0();
        __syncthreads();
        if (c + 1 < G2_KIT) CPA2(c + 1, st ^ 1);
        COMP2(st);
        if (c + 1 < G2_KIT) STSB2(st ^ 1);
        if (c + 2 < G2_KIT) LDGB2(c + 2);
    }
    __syncthreads();

    // C -> smem fp32 [128][132]
    float* sc = (float*)sp;
#pragma unroll
    for (int mt = 0; mt < 4; mt++)
#pragma unroll
        for (int nt = 0; nt < 8; nt++) {
            int r0 = wm * 64 + mt * 16 + (lane >> 2);
            int cc = wn * 64 + nt * 8 + (lane & 3) * 2;
            sc[r0 * 132 + cc]       = C[mt][nt][0];
            sc[r0 * 132 + cc + 1]   = C[mt][nt][1];
            sc[(r0 + 8) * 132 + cc]     = C[mt][nt][2];
            sc[(r0 + 8) * 132 + cc + 1] = C[mt][nt][3];
        }
    __syncthreads();

    // coalesced STG of partials: warp writes a full 512B row per instr
    {
        float* dst = g_y + ((size_t)kh * MAX_SLOTS + base) * Dn + d0;
#pragma unroll
        for (int r = warp; r < TILE_M; r += 4) {
            float4 v = *(float4*)&sc[r * 132 + lane * 4];
            *(float4*)(dst + (size_t)r * Dn + lane * 4) = v;
        }
    }
#undef LDGB2
#undef CPA2
#undef STSB2
#undef COMP2
}

// ---------------------------------------------------------------------------
extern "C" void kernel_launch(void* const* d_in, const int* in_sizes, int n_in,
                              void* d_out, int out_size) {
    const float* x   = (const float*)d_in[0];
    const float* wts = (const float*)d_in[1];
    const int*   sel = (const int*)d_in[2];
    const float* w1  = (const float*)d_in[3];
    const float* w2  = (const float*)d_in[4];
    const float* w3  = (const float*)d_in[5];
    float* out = (float*)d_out;

    cudaFuncSetAttribute(gemm1_kernel,
                         cudaFuncAttributeMaxDynamicSharedMemorySize, SMEM_REQ);
    cudaFuncSetAttribute(gemm2_kernel,
                         cudaFuncAttributeMaxDynamicSharedMemorySize, SMEM_REQ);

    route_kernel<<<1, 1024>>>(sel, wts);
    splitx_kernel<<<(Tn * Dn) / 1024, 256>>>((const float4*)x, (Tn * Dn) / 4);
    // tile index fastest: all M-tiles of one weight tile run concurrently,
    // weights stream from DRAM once and reuse via L2.
    gemm1_kernel<<<dim3(MAX_TILES, Hn / 64), 128, SMEM_REQ>>>(w1, w3);
    gemm2_kernel<<<dim3(MAX_TILES, Dn / 128, 2), 128, SMEM_REQ>>>(w2);
    combine_kernel<<<(Tn * Dn / 4) / 256, 256>>>(wts, out);
}

// round 15
// speedup vs baseline: 1.2965x; 1.0562x over previous
#include <cuda_runtime.h>
#include <cuda_fp16.h>
#include <cstdint>

// Problem constants
#define Tn 1024
#define Dn 2048
#define Hn 7168
#define En 8
#define Kn 2
#define Pn (Tn * Kn)                   // 2048 (token,k) pairs
#define TILE_M 128
#define MAX_SLOTS (Pn + En * TILE_M)   // 3072
#define MAX_TILES (Pn / TILE_M + En)   // 24

#define G1_KIT (Dn / 32)               // 64 K-chunks of 32
#define G2_HALF (Hn / 2)               // 3584
#define G2_KIT (G2_HALF / 32)          // 112 K-chunks per half

// Dynamic smem: 2 stages x 32KB + slack (epilogue reuses as 128x132 fp32)
#define SMEM_REQ 68608

// Scratch (device globals; no allocation allowed)
__device__ int   g_slot_token[MAX_SLOTS];
__device__ float g_slot_w[MAX_SLOTS];
__device__ int   g_tile_expert[MAX_TILES];
__device__ int   g_tile_base[MAX_TILES];
__device__ int   g_pair_slot[Pn];
// single fp16 plane for the A-side operands
__device__ __align__(16) unsigned short g_x_h[(size_t)Tn * Dn];
__device__ __align__(16) unsigned short g_hact_h[(size_t)MAX_SLOTS * Hn];
// per-half, per-slot gemm2 partials (~50 MB)
__device__ __align__(16) float g_y[(size_t)2 * MAX_SLOTS * Dn];

// ---------------------------------------------------------------------------
// Helpers
// ---------------------------------------------------------------------------
__device__ __forceinline__ uint32_t smem_u32(const void* p) {
    uint32_t a;
    asm("{ .reg .u64 t; cvta.to.shared.u64 t, %1; cvt.u32.u64 %0, t; }"
        : "=r"(a) : "l"(p));
    return a;
}

__device__ __forceinline__ uint32_t sw128(uint32_t o) {
    return o ^ (((o >> 7) & 7u) << 4);
}
__device__ __forceinline__ uint32_t sw256(uint32_t o) {
    return o ^ (((o >> 8) & 7u) << 4);
}

__device__ __forceinline__ void cpa16(uint32_t dst, const void* src, uint32_t sz) {
    asm volatile("cp.async.cg.shared.global [%0], [%1], 16, %2;"
                 :: "r"(dst), "l"(src), "r"(sz) : "memory");
}
#define CP_COMMIT() asm volatile("cp.async.commit_group;" ::: "memory")
#define CP_WAIT0()  asm volatile("cp.async.wait_group 0;" ::: "memory")

__device__ __forceinline__ void ldsm4(uint32_t* r, uint32_t a) {
    asm volatile("ldmatrix.sync.aligned.m8n8.x4.shared.b16 {%0,%1,%2,%3}, [%4];"
        : "=r"(r[0]), "=r"(r[1]), "=r"(r[2]), "=r"(r[3]) : "r"(a));
}
__device__ __forceinline__ void ldsm4t(uint32_t* r, uint32_t a) {
    asm volatile("ldmatrix.sync.aligned.m8n8.x4.trans.shared.b16 {%0,%1,%2,%3}, [%4];"
        : "=r"(r[0]), "=r"(r[1]), "=r"(r[2]), "=r"(r[3]) : "r"(a));
}
__device__ __forceinline__ void mma16816h(float* c, const uint32_t* a,
                                          uint32_t b0, uint32_t b1) {
    asm volatile(
        "mma.sync.aligned.m16n8k16.row.col.f32.f16.f16.f32 "
        "{%0,%1,%2,%3}, {%4,%5,%6,%7}, {%8,%9}, {%0,%1,%2,%3};"
        : "+f"(c[0]), "+f"(c[1]), "+f"(c[2]), "+f"(c[3])
        : "r"(a[0]), "r"(a[1]), "r"(a[2]), "r"(a[3]), "r"(b0), "r"(b1));
}

__device__ __forceinline__ uint32_t ph_rn(float a, float b) {
    __half2 h = __floats2half2_rn(a, b);
    return *(uint32_t*)&h;
}

// ---------------------------------------------------------------------------
// x convert: fp32 -> fp16 plane (4 MB, ~4us)
// ---------------------------------------------------------------------------
__global__ void splitx_kernel(const float4* __restrict__ src, int n4) {
    int i = blockIdx.x * blockDim.x + threadIdx.x;
    if (i < n4) {
        float4 v = __ldg(src + i);
        ((uint2*)g_x_h)[i] = make_uint2(ph_rn(v.x, v.y), ph_rn(v.z, v.w));
    }
}

// ---------------------------------------------------------------------------
// Routing: atomic per-expert fill. Slot order within an expert is arbitrary;
// output is invariant to it (per-row math identical in any row position,
// combine reads through g_pair_slot) -> output stays bit-deterministic.
// ---------------------------------------------------------------------------
__global__ void route_kernel(const int* __restrict__ sel,
                             const float* __restrict__ wts) {
    __shared__ int s_cnt[En];
    __shared__ int s_base[En];
    __shared__ int s_fill[En];
    int tid = threadIdx.x;

    if (tid < En) { s_cnt[tid] = 0; s_fill[tid] = 0; }
    __syncthreads();
    for (int i = tid; i < Pn; i += blockDim.x)
        atomicAdd(&s_cnt[sel[i]], 1);
    __syncthreads();
    if (tid == 0) {
        int base = 0, tile = 0;
        for (int e = 0; e < En; e++) {
            s_base[e] = base;
            int padded = ((s_cnt[e] + TILE_M - 1) / TILE_M) * TILE_M;
            for (int m = 0; m < padded; m += TILE_M) {
                g_tile_expert[tile] = e;
                g_tile_base[tile]   = base + m;
                tile++;
            }
            base += padded;
        }
        for (; tile < MAX_TILES; tile++) g_tile_expert[tile] = -1;
    }
    __syncthreads();
    for (int s = tid; s < MAX_SLOTS; s += blockDim.x) g_slot_token[s] = -1;
    __syncthreads();
    for (int i = tid; i < Pn; i += blockDim.x) {
        int e = sel[i];
        int r = atomicAdd(&s_fill[e], 1);
        int slot = s_base[e] + r;
        g_slot_token[slot] = i / Kn;
        g_slot_w[slot]     = wts[i];
        g_pair_slot[i]     = slot;
    }
}

// ---------------------------------------------------------------------------
// Combine: out[t,d] = w0*(y0h0+y0h1) + w1*(y1h0+y1h1)   (fixed order, determ.)
// ---------------------------------------------------------------------------
__global__ void combine_kernel(const float* __restrict__ wts,
                               float* __restrict__ out) {
    int i = blockIdx.x * blockDim.x + threadIdx.x;   // over Tn*Dn/4
    int tok = i >> 9;                                 // Dn/4 = 512
    int d4 = i & 511;
    int s0 = g_pair_slot[2 * tok], s1 = g_pair_slot[2 * tok + 1];
    float w0 = wts[2 * tok], w1 = wts[2 * tok + 1];
    const float4* y = (const float4*)g_y;
    const size_t n4 = Dn / 4;
    float4 a = y[(size_t)s0 * n4 + d4];
    float4 b = y[((size_t)MAX_SLOTS + s0) * n4 + d4];
    float4 c = y[(size_t)s1 * n4 + d4];
    float4 d = y[((size_t)MAX_SLOTS + s1) * n4 + d4];
    float4 o;
    o.x = w0 * (a.x + b.x) + w1 * (c.x + d.x);
    o.y = w0 * (a.y + b.y) + w1 * (c.y + d.y);
    o.z = w0 * (a.z + b.z) + w1 * (c.z + d.z);
    o.w = w0 * (a.w + b.w) + w1 * (c.w + d.w);
    ((float4*)out)[i] = o;
}

// ---------------------------------------------------------------------------
// GEMM1: hact[slot, h0+c] = silu(x.W1^T) * (x.W3^T)   [R11 mainloop]
// Plain fp16. CTA 128x128 (n 0-63 gate / 64-127 up), BK=32, 4 warps 64x64.
// ---------------------------------------------------------------------------
__global__ __launch_bounds__(128, 2) void gemm1_kernel(
    const float* __restrict__ w1,
    const float* __restrict__ w3) {
    int e = g_tile_expert[blockIdx.x];
    if (e < 0) return;
    int base = g_tile_base[blockIdx.x];
    int h0 = blockIdx.y * 64;

    extern __shared__ char dsm[];
    __shared__ int s_tok[TILE_M];
    uint32_t raw = smem_u32(dsm);
    uint32_t sb = (raw + 1023u) & ~1023u;
    char* sp = dsm + (sb - raw);

    int tid = threadIdx.x;
    s_tok[tid] = g_slot_token[base + tid];
    __syncthreads();

    const int warp = tid >> 5, lane = tid & 31;
    const int wm = warp & 1, wn = warp >> 1;   // 2m x 2n, warp tile 64x64

    // A: thread t serves rows g*32+(t>>2), granule t&3 (16B of a 64B row run)
    const unsigned short* aP[4];
    uint32_t avz[4], adst[4];
#pragma unroll
    for (int g = 0; g < 4; g++) {
        int r = g * 32 + (tid >> 2);
        int tk = s_tok[r];
        aP[g]  = g_x_h + (size_t)(tk < 0 ? 0 : tk) * Dn + (tid & 3) * 8;
        avz[g] = (tk >= 0) ? 16u : 0u;
        adst[g] = sw128((uint32_t)r * 128u + (uint32_t)(tid & 3) * 16u);
    }

    // B: thread t serves rows g*16+(t>>3), seg t&7 (16B fp32 -> 8B fp16)
    const float* b1P = w1 + ((size_t)e * Hn + h0 + (tid >> 3)) * Dn + (tid & 7) * 4;
    const float* b3P = w3 + ((size_t)e * Hn + h0 + (tid >> 3)) * Dn + (tid & 7) * 4;
    uint32_t bdst[8];
#pragma unroll
    for (int g = 0; g < 8; g++) {
        uint32_t r = (uint32_t)(g * 16 + (tid >> 3));
        bdst[g] = sw128(r * 128u + (uint32_t)((tid & 7) >> 1) * 16u)
                + (uint32_t)((tid & 7) & 1) * 8u;
    }

    // ldmatrix lane offsets
    const uint32_t a_m  = (uint32_t)(lane & 15);
    const uint32_t a_kc = (uint32_t)(lane >> 4);
    const uint32_t b_n  = (uint32_t)((lane & 7) | ((lane >> 4) << 3));
    const uint32_t b_kc = (uint32_t)((lane >> 3) & 1);

    float C[4][8][4];
#pragma unroll
    for (int i = 0; i < 4; i++)
#pragma unroll
        for (int j = 0; j < 8; j++)
#pragma unroll
            for (int k = 0; k < 4; k++) C[i][j][k] = 0.f;

    float4 Br[8];

#define LDGB1(c) do {                                                       \
    _Pragma("unroll")                                                       \
    for (int g = 0; g < 4; g++)                                             \
        Br[g] = __ldg((const float4*)(b1P + (size_t)g * 16 * Dn + (c) * 32)); \
    _Pragma("unroll")                                                       \
    for (int g = 4; g < 8; g++)                                             \
        Br[g] = __ldg((const float4*)(b3P + (size_t)(g - 4) * 16 * Dn + (c) * 32)); \
} while (0)

#define CPA1(c, st) do {                                                    \
    uint32_t Ab = sb + (st) * 32768u;                                       \
    _Pragma("unroll")                                                       \
    for (int g = 0; g < 4; g++)                                             \
        cpa16(Ab + adst[g], aP[g] + (c) * 32, avz[g]);                      \
    CP_COMMIT();                                                            \
} while (0)

#define STSB1(st) do {                                                      \
    char* Bb = sp + (st) * 32768 + 16384;                                   \
    _Pragma("unroll")                                                       \
    for (int g = 0; g < 8; g++) {                                           \
        float4 v = Br[g];                                                   \
        *(uint2*)(Bb + bdst[g]) = make_uint2(ph_rn(v.x, v.y), ph_rn(v.z, v.w)); \
    }                                                                       \
} while (0)

#define COMP1(st) do {                                                      \
    uint32_t Au = sb + (st) * 32768u;                                       \
    uint32_t Bu = Au + 16384u;                                              \
    _Pragma("unroll")                                                       \
    for (int k16 = 0; k16 < 2; k16++) {                                     \
        uint32_t aH[4][4];                                                  \
        _Pragma("unroll")                                                   \
        for (int mt = 0; mt < 4; mt++) {                                    \
            uint32_t o = (uint32_t)(wm * 64 + mt * 16 + a_m) * 128u + k16 * 32u + a_kc * 16u; \
            ldsm4(aH[mt], Au + sw128(o));                                   \
        }                                                                   \
        _Pragma("unroll")                                                   \
        for (int ng = 0; ng < 4; ng++) {                                    \
            uint32_t o = (uint32_t)(wn * 64 + ng * 16 + b_n) * 128u + k16 * 32u + b_kc * 16u; \
            uint32_t bH[4];                                                 \
            ldsm4(bH, Bu + sw128(o));                                       \
            _Pragma("unroll")                                               \
            for (int mt = 0; mt < 4; mt++) {                                \
                mma16816h(C[mt][2 * ng],     aH[mt], bH[0], bH[1]);         \
                mma16816h(C[mt][2 * ng + 1], aH[mt], bH[2], bH[3]);         \
            }                                                               \
        }                                                                   \
    }                                                                       \
} while (0)

    LDGB1(0);
    CPA1(0, 0);
    STSB1(0);
    LDGB1(1);
    for (int c = 0; c < G1_KIT; c++) {
        int st = c & 1;
        CP_WAIT0();
        __syncthreads();
        if (c + 1 < G1_KIT) CPA1(c + 1, st ^ 1);
        COMP1(st);
        if (c + 1 < G1_KIT) STSB1(st ^ 1);
        if (c + 2 < G1_KIT) LDGB1(c + 2);
    }
    __syncthreads();

    // C -> smem fp32 [128][132]
    float* sc = (float*)sp;
#pragma unroll
    for (int mt = 0; mt < 4; mt++)
#pragma unroll
        for (int nt = 0; nt < 8; nt++) {
            int r0 = wm * 64 + mt * 16 + (lane >> 2);
            int cc = wn * 64 + nt * 8 + (lane & 3) * 2;
            sc[r0 * 132 + cc]       = C[mt][nt][0];
            sc[r0 * 132 + cc + 1]   = C[mt][nt][1];
            sc[(r0 + 8) * 132 + cc]     = C[mt][nt][2];
            sc[(r0 + 8) * 132 + cc + 1] = C[mt][nt][3];
        }
    __syncthreads();

    // SiLU(gate)*up -> g_hact fp16 plane; thread t owns row t (64 outputs)
    {
        size_t orow = (size_t)(base + tid) * Hn + h0;
#pragma unroll
        for (int j = 0; j < 64; j += 4) {
            float v[4];
#pragma unroll
            for (int jj = 0; jj < 4; jj++) {
                float g = sc[tid * 132 + j + jj];
                float u = sc[tid * 132 + 64 + j + jj];
                v[jj] = g / (1.f + __expf(-g)) * u;
            }
            *(uint2*)(g_hact_h + orow + j) =
                make_uint2(ph_rn(v[0], v[1]), ph_rn(v[2], v[3]));
        }
    }
#undef LDGB1
#undef CPA1
#undef STSB1
#undef COMP1
}

// ---------------------------------------------------------------------------
// GEMM2 (K-split x2): g_y[half][slot, d0+c] = sum_{h in half} hact*w2
// Plain fp16, CTA 128x128, 4 warps 64x64, 2-stage pipeline, STG epilogue.
// ---------------------------------------------------------------------------
__global__ __launch_bounds__(128, 2) void gemm2_kernel(
    const float* __restrict__ w2) {
    int e = g_tile_expert[blockIdx.x];
    if (e < 0) return;
    int base = g_tile_base[blockIdx.x];
    int d0 = blockIdx.y * 128;
    int kh = blockIdx.z;
    const int hoff = kh * G2_HALF;

    extern __shared__ char dsm[];
    uint32_t raw = smem_u32(dsm);
    uint32_t sb = (raw + 1023u) & ~1023u;
    char* sp = dsm + (sb - raw);

    int tid = threadIdx.x;
    const int warp = tid >> 5, lane = tid & 31;
    const int wm = warp & 1, wn = warp >> 1;

    // A: thread t serves rows g*32+(t>>2), granule t&3
    const unsigned short* aP[4];
    uint32_t adst[4];
#pragma unroll
    for (int g = 0; g < 4; g++) {
        int r = g * 32 + (tid >> 2);
        aP[g]   = g_hact_h + (size_t)(base + r) * Hn + hoff + (tid & 3) * 8;
        adst[g] = sw128((uint32_t)r * 128u + (uint32_t)(tid & 3) * 16u);
    }

    // B: warp reads k-row g*4+warp, lane covers seg=lane (16B fp32 -> 8B)
    const float* wP = w2 + ((size_t)e * Hn + hoff + warp) * Dn + d0 + lane * 4;
    uint32_t bdst[8];
#pragma unroll
    for (int g = 0; g < 8; g++) {
        uint32_t r = (uint32_t)(g * 4 + warp);
        bdst[g] = sw256(r * 256u + (uint32_t)(lane >> 1) * 16u)
                + (uint32_t)(lane & 1) * 8u;
    }

    // ldmatrix lane offsets
    const uint32_t a_m  = (uint32_t)(lane & 15);
    const uint32_t a_kc = (uint32_t)(lane >> 4);
    const uint32_t t_k  = (uint32_t)((lane & 7) | (((lane >> 3) & 1) << 3));
    const uint32_t t_n8 = (uint32_t)(lane >> 4);

    float C[4][8][4];
#pragma unroll
    for (int i = 0; i < 4; i++)
#pragma unroll
        for (int j = 0; j < 8; j++)
#pragma unroll
            for (int k = 0; k < 4; k++) C[i][j][k] = 0.f;

    float4 Br[8];

#define LDGB2(c) do {                                                       \
    _Pragma("unroll")                                                       \
    for (int g = 0; g < 8; g++)                                             \
        Br[g] = __ldg((const float4*)(wP + ((size_t)(c) * 32 + g * 4) * Dn)); \
} while (0)

#define CPA2(c, st) do {                                                    \
    uint32_t Ab = sb + (st) * 32768u;                                       \
    _Pragma("unroll")                                                       \
    for (int g = 0; g < 4; g++)                                             \
        cpa16(Ab + adst[g], aP[g] + (c) * 32, 16u);                         \
    CP_COMMIT();                                                            \
} while (0)

#define STSB2(st) do {                                                      \
    char* Bh = sp + (st) * 32768 + 16384;                                   \
    _Pragma("unroll")                                                       \
    for (int g = 0; g < 8; g++) {                                           \
        float4 v = Br[g];                                                   \
        *(uint2*)(Bh + bdst[g]) = make_uint2(ph_rn(v.x, v.y), ph_rn(v.z, v.w)); \
    }                                                                       \
} while (0)

#define COMP2(st) do {                                                      \
    uint32_t Au  = sb + (st) * 32768u;                                      \
    uint32_t Bhu = Au + 16384u;                                             \
    _Pragma("unroll")                                                       \
    for (int k16 = 0; k16 < 2; k16++) {                                     \
        uint32_t aH[4][4];                                                  \
        _Pragma("unroll")                                                   \
        for (int mt = 0; mt < 4; mt++) {                                    \
            uint32_t o = (uint32_t)(wm * 64 + mt * 16 + a_m) * 128u + k16 * 32u + a_kc * 16u; \
            ldsm4(aH[mt], Au + sw128(o));                                   \
        }                                                                   \
        _Pragma("unroll")                                                   \
        for (int ng = 0; ng < 4; ng++) {                                    \
            uint32_t o = (k16 * 16u + t_k) * 256u                           \
                       + (uint32_t)(wn * 64 + ng * 16) * 2u + t_n8 * 16u;   \
            uint32_t bH[4];                                                 \
            ldsm4t(bH, Bhu + sw256(o));                                     \
            _Pragma("unroll")                                               \
            for (int mt = 0; mt < 4; mt++) {                                \
                mma16816h(C[mt][2 * ng],     aH[mt], bH[0], bH[1]);         \
                mma16816h(C[mt][2 * ng + 1], aH[mt], bH[2], bH[3]);         \
            }                                                               \
        }                                                                   \
    }                                                                       \
} while (0)

    LDGB2(0);
    CPA2(0, 0);
    STSB2(0);
    LDGB2(1);
    for (int c = 0; c < G2_KIT; c++) {
        int st = c & 1;
        CP_WAIT0();
        __syncthreads();
        if (c + 1 < G2_KIT) CPA2(c + 1, st ^ 1);
        COMP2(st);
        if (c + 1 < G2_KIT) STSB2(st ^ 1);
        if (c + 2 < G2_KIT) LDGB2(c + 2);
    }
    __syncthreads();

    // C -> smem fp32 [128][132]
    float* sc = (float*)sp;
#pragma unroll
    for (int mt = 0; mt < 4; mt++)
#pragma unroll
        for (int nt = 0; nt < 8; nt++) {
            int r0 = wm * 64 + mt * 16 + (lane >> 2);
            int cc = wn * 64 + nt * 8 + (lane & 3) * 2;
            sc[r0 * 132 + cc]       = C[mt][nt][0];
            sc[r0 * 132 + cc + 1]   = C[mt][nt][1];
            sc[(r0 + 8) * 132 + cc]     = C[mt][nt][2];
            sc[(r0 + 8) * 132 + cc + 1] = C[mt][nt][3];
        }
    __syncthreads();

    // coalesced STG of partials: warp writes a full 512B row per instr
    {
        float* dst = g_y + ((size_t)kh * MAX_SLOTS + base) * Dn + d0;
#pragma unroll
        for (int r = warp; r < TILE_M; r += 4) {
            float4 v = *(float4*)&sc[r * 132 + lane * 4];
            *(float4*)(dst + (size_t)r * Dn + lane * 4) = v;
        }
    }
#undef LDGB2
#undef CPA2
#undef STSB2
#undef COMP2
}

// ---------------------------------------------------------------------------
extern "C" void kernel_launch(void* const* d_in, const int* in_sizes, int n_in,
                              void* d_out, int out_size) {
    const float* x   = (const float*)d_in[0];
    const float* wts = (const float*)d_in[1];
    const int*   sel = (const int*)d_in[2];
    const float* w1  = (const float*)d_in[3];
    const float* w2  = (const float*)d_in[4];
    const float* w3  = (const float*)d_in[5];
    float* out = (float*)d_out;

    cudaFuncSetAttribute(gemm1_kernel,
                         cudaFuncAttributeMaxDynamicSharedMemorySize, SMEM_REQ);
    cudaFuncSetAttribute(gemm2_kernel,
                         cudaFuncAttributeMaxDynamicSharedMemorySize, SMEM_REQ);

    route_kernel<<<1, 1024>>>(sel, wts);
    splitx_kernel<<<(Tn * Dn) / 1024, 256>>>((const float4*)x, (Tn * Dn) / 4);
    // tile index fastest: all M-tiles of one weight tile run concurrently,
    // weights stream from DRAM once and reuse via L2.
    gemm1_kernel<<<dim3(MAX_TILES, Hn / 64), 128, SMEM_REQ>>>(w1, w3);
    gemm2_kernel<<<dim3(MAX_TILES, Dn / 128, 2), 128, SMEM_REQ>>>(w2);
    combine_kernel<<<(Tn * Dn / 4) / 256, 256>>>(wts, out);
}